// round 8
// baseline (speedup 1.0000x reference)
#include <cuda_runtime.h>
#include <cstdint>

// Problem constants
#define Nn 8192
#define Dd 256
#define NBLK 64           // 8192 / 128
#define NTILES 2080       // upper triangle incl diagonal: 64*65/2
#define GRID_MAIN 152
#define MAXC 256          // per-class row cap (11 sigma above mean 128)

// Main SMEM layout: 2 stages x (A 32KB + B 32KB) + reduction
#define STAGE_SZ 32768
#define SM_AOFF(s) ((s) * STAGE_SZ)
#define SM_BOFF(s) (65536 + (s) * STAGE_SZ)
#define SM_RED 131072
#define SM_TOTAL 135168

// Pos SMEM layout
#define PS_A 0
#define PS_B 32768
#define PS_RED 65536      // 256 floats
#define PS_SELF 66560     // 128 floats
#define PS_TOTAL 67584

// scale folds 1/T and log2(e):  sqrt(10 * log2(e))
#define SCALE_C 3.79828197f

// Scratch (__device__ globals: allocation-free rule)
__device__ uint8_t g_Q[Nn * Dd];      // e4m3 rows of u * SCALE_C
__device__ uint8_t g_zero[256];       // zero row for padding (zero-initialized)
__device__ int   g_cls[Nn];
__device__ int   g_perm[NBLK * MAXC];
__device__ int   g_cnt[NBLK];
__device__ float g_totP[NBLK * Nn];
__device__ float g_posI[Nn];
__device__ float g_posE[Nn];
__device__ float g_lossP[64];
__device__ unsigned char g_ti[NTILES], g_tj[NTILES];

// ---------------- PTX helpers (family-safe) ----------------
__device__ __forceinline__ uint32_t smem_u32(const void* p) {
    uint32_t a;
    asm("{ .reg .u64 t; cvta.to.shared.u64 t, %1; cvt.u32.u64 %0, t; }" : "=r"(a) : "l"(p));
    return a;
}
#define CP16(dst, src) asm volatile("cp.async.cg.shared.global [%0], [%1], 16;" :: "r"(dst), "l"(src))
#define CP_COMMIT() asm volatile("cp.async.commit_group;" ::: "memory")
#define CP_WAIT0() asm volatile("cp.async.wait_group 0;" ::: "memory")
#define CP_WAIT1() asm volatile("cp.async.wait_group 1;" ::: "memory")

#define LDM4(r, a) \
    asm volatile("ldmatrix.sync.aligned.m8n8.x4.shared.b16 {%0,%1,%2,%3}, [%4];" \
        : "=r"((r)[0]), "=r"((r)[1]), "=r"((r)[2]), "=r"((r)[3]) : "r"(a))

#define QMMA(c, a, b0, b1) \
    asm volatile("mma.sync.aligned.m16n8k32.row.col.f32.e4m3.e4m3.f32 " \
        "{%0,%1,%2,%3}, {%4,%5,%6,%7}, {%8,%9}, {%0,%1,%2,%3};" \
        : "+f"((c)[0]), "+f"((c)[1]), "+f"((c)[2]), "+f"((c)[3]) \
        : "r"((a)[0]), "r"((a)[1]), "r"((a)[2]), "r"((a)[3]), "r"(b0), "r"(b1))

__device__ __forceinline__ float ex2f(float x) {
    float r;
    asm("ex2.approx.f32 %0, %1;" : "=f"(r) : "f"(x));
    return r;
}
__device__ __forceinline__ unsigned long long pack2(float lo, float hi) {
    unsigned long long r;
    asm("mov.b64 %0, {%1,%2};" : "=l"(r) : "f"(lo), "f"(hi));
    return r;
}
__device__ __forceinline__ void unpack2(unsigned long long v, float& lo, float& hi) {
    asm("mov.b64 {%0,%1}, %2;" : "=f"(lo), "=f"(hi) : "l"(v));
}
#define ADD2(d, a) asm("add.rn.f32x2 %0, %0, %1;" : "+l"(d) : "l"(a))

// e4m3 pack: first PTX src -> HIGH byte, second -> LOW byte
__device__ __forceinline__ uint16_t fp8x2(float loVal, float hiVal) {
    uint16_t r;
    asm("cvt.rn.satfinite.e4m3x2.f32 %0, %1, %2;" : "=h"(r) : "f"(hiVal), "f"(loVal));
    return r;
}

// ---------------- setup: dtype detect + class extraction + tile map ----------------
__global__ void detcls_kernel(const void* __restrict__ tgt) {
    __shared__ int sflag;
    const int* t32 = (const int*)tgt;
    int tid = threadIdx.x;
    int acc = 0;
    for (int k = tid; k < Nn / 2; k += 256) acc |= t32[2 * k + 1];
    acc = __reduce_or_sync(0xffffffffu, acc);
    __shared__ int sor[8];
    if ((tid & 31) == 0) sor[tid >> 5] = acc;
    __syncthreads();
    if (tid == 0) {
        int v = 0;
#pragma unroll
        for (int i = 0; i < 8; i++) v |= sor[i];
        sflag = (v == 0) ? 1 : 0;
    }
    __syncthreads();
    int is64 = sflag;
    const long long* t64 = (const long long*)tgt;
    for (int r = tid; r < Nn; r += 256)
        g_cls[r] = is64 ? (int)t64[r] : t32[r];
    for (int tt = tid; tt < NTILES; tt += 256) {
        int i = 0, rem = tt;
        while (rem >= NBLK - i) { rem -= NBLK - i; i++; }
        g_ti[tt] = (unsigned char)i;
        g_tj[tt] = (unsigned char)(i + rem);
    }
}

// ---------------- stable class bucketing: one block per class ----------------
__global__ void bucket_kernel() {
    int c = blockIdx.x;
    int tid = threadIdx.x;
    int base = tid * 32;
    int m = 0;
#pragma unroll 4
    for (int k = 0; k < 32; k++) m += (g_cls[base + k] == c) ? 1 : 0;
    __shared__ int s[256];
    s[tid] = m;
    __syncthreads();
    for (int off = 1; off < 256; off <<= 1) {
        int v = (tid >= off) ? s[tid - off] : 0;
        __syncthreads();
        s[tid] += v;
        __syncthreads();
    }
    int w = s[tid] - m;      // exclusive prefix
    int cnt = s[255];
    for (int k = 0; k < 32; k++) {
        if (g_cls[base + k] == c) {
            if (w < MAXC) g_perm[c * MAXC + w] = base + k;
            w++;
        }
    }
    if (tid == 0) g_cnt[c] = cnt < MAXC ? cnt : MAXC;
}

// ---------------- normalize + e4m3 quantize: warp per row ----------------
__global__ void norm_kernel(const float* __restrict__ emb) {
    int tid = threadIdx.x, lane = tid & 31, wid = tid >> 5;
    int row = blockIdx.x * 8 + wid;
    const float4* src = (const float4*)&emb[row * Dd + lane * 8];
    float4 v0 = src[0], v1 = src[1];
    float v[8] = {v0.x, v0.y, v0.z, v0.w, v1.x, v1.y, v1.z, v1.w};
    float sq = 0.f;
#pragma unroll
    for (int i = 0; i < 8; i++) sq += v[i] * v[i];
#pragma unroll
    for (int o = 16; o > 0; o >>= 1) sq += __shfl_xor_sync(0xffffffffu, sq, o);
    float scale = SCALE_C / fmaxf(sqrtf(sq), 1e-8f);
    uint16_t p01 = fp8x2(v[0] * scale, v[1] * scale);
    uint16_t p23 = fp8x2(v[2] * scale, v[3] * scale);
    uint16_t p45 = fp8x2(v[4] * scale, v[5] * scale);
    uint16_t p67 = fp8x2(v[6] * scale, v[7] * scale);
    uint32_t lo = (uint32_t)p01 | ((uint32_t)p23 << 16);
    uint32_t hi = (uint32_t)p45 | ((uint32_t)p67 << 16);
    *(uint2*)&g_Q[row * Dd + lane * 8] = make_uint2(lo, hi);
}

// ---------------- main fused symmetric FP8-MMA kernel (tot only) ----------------
__device__ __forceinline__ void loadChunk(uint32_t sb, int stage, int blkA, int blkB, int tid) {
    uint32_t aBase = sb + SM_AOFF(stage);
    uint32_t bBase = sb + SM_BOFF(stage);
#pragma unroll
    for (int it = 0; it < 8; it++) {
        int idx = it * 256 + tid;
        int r = idx >> 4, c = idx & 15;
        uint32_t off = r * 256 + ((c ^ (r & 7)) << 4);
        CP16(aBase + off, (const char*)&g_Q[(blkA * 128 + r) * Dd] + c * 16);
        CP16(bBase + off, (const char*)&g_Q[(blkB * 128 + r) * Dd] + c * 16);
    }
    CP_COMMIT();
}

__global__ void __launch_bounds__(256, 1) main_kernel() {
    extern __shared__ char smem[];
    uint32_t sb = smem_u32(smem);
    int tid = threadIdx.x, lane = tid & 31, wid = tid >> 5;
    int wr = wid & 3, wc = wid >> 2;          // 4 row-warps x 2 col-warps
    int laneHi = lane >> 4;

    uint32_t rowOffA[2]; int axor[2];
#pragma unroll
    for (int i = 0; i < 2; i++) {
        int r = wr * 32 + i * 16 + (lane & 15);
        rowOffA[i] = r * 256; axor[i] = r & 7;
    }
    uint32_t rowOffB[4]; int bxor[4];
#pragma unroll
    for (int g = 0; g < 4; g++) {
        int r = wc * 64 + g * 16 + (lane & 15);
        rowOffB[g] = r * 256; bxor[g] = r & 7;
    }
    int li[4];
#pragma unroll
    for (int s = 0; s < 4; s++) li[s] = wr * 32 + (s >> 1) * 16 + (s & 1) * 8 + (lane >> 2);

    float* redRowT = (float*)(smem + SM_RED);            // 256 floats
    float* redColT = redRowT + 256;                      // 512 floats

    int t0 = blockIdx.x;
    if (t0 >= NTILES) return;
    int bi = g_ti[t0], bj = g_tj[t0];
    loadChunk(sb, 0, bi, bj, tid);

    int stage = 0;
    for (int t = t0; t < NTILES; t += GRID_MAIN) {
        bool isDiag = (bi == bj);
        int nt = t + GRID_MAIN;
        int nbi = 0, nbj = 0;
        if (nt < NTILES) {
            nbi = g_ti[nt]; nbj = g_tj[nt];
            loadChunk(sb, stage ^ 1, nbi, nbj, tid);
            CP_WAIT1();
        } else {
            CP_WAIT0();
        }
        __syncthreads();

        float cAcc[2][8][4];
#pragma unroll
        for (int i = 0; i < 2; i++)
#pragma unroll
            for (int n = 0; n < 8; n++)
#pragma unroll
                for (int v = 0; v < 4; v++) cAcc[i][n][v] = 0.f;

        uint32_t aB = sb + SM_AOFF(stage), bB = sb + SM_BOFF(stage);
#pragma unroll
        for (int ks = 0; ks < 8; ks++) {
            uint32_t a[2][4], b[4][4];
            int ch = ks * 2 + laneHi;
#pragma unroll
            for (int i = 0; i < 2; i++) LDM4(a[i], aB + rowOffA[i] + ((ch ^ axor[i]) << 4));
#pragma unroll
            for (int g = 0; g < 4; g++) LDM4(b[g], bB + rowOffB[g] + ((ch ^ bxor[g]) << 4));
#pragma unroll
            for (int i = 0; i < 2; i++)
#pragma unroll
                for (int n = 0; n < 8; n++)
                    QMMA(cAcc[i][n], a[i], b[n >> 1][n & 1], b[n >> 1][(n & 1) + 2]);
        }

        // ---- minimal epilogue: ex2 + packed row/col totals, no masks ----
        unsigned long long rowTot2[4] = {0ull, 0ull, 0ull, 0ull};
        unsigned long long colTot2[8];
#pragma unroll
        for (int n = 0; n < 8; n++) colTot2[n] = 0ull;

        if (isDiag) {
#pragma unroll
            for (int n = 0; n < 8; n++) {
#pragma unroll
                for (int i = 0; i < 2; i++) {
                    float e0 = ex2f(cAcc[i][n][0]);
                    float e1 = ex2f(cAcc[i][n][1]);
                    float e2 = ex2f(cAcc[i][n][2]);
                    float e3 = ex2f(cAcc[i][n][3]);
                    ADD2(rowTot2[2 * i], pack2(e0, e1));
                    ADD2(rowTot2[2 * i + 1], pack2(e2, e3));
                }
            }
        } else {
#pragma unroll
            for (int n = 0; n < 8; n++) {
#pragma unroll
                for (int i = 0; i < 2; i++) {
                    float e0 = ex2f(cAcc[i][n][0]);
                    float e1 = ex2f(cAcc[i][n][1]);
                    float e2 = ex2f(cAcc[i][n][2]);
                    float e3 = ex2f(cAcc[i][n][3]);
                    unsigned long long p01 = pack2(e0, e1);
                    unsigned long long p23 = pack2(e2, e3);
                    ADD2(rowTot2[2 * i], p01);
                    ADD2(rowTot2[2 * i + 1], p23);
                    ADD2(colTot2[n], p01);
                    ADD2(colTot2[n], p23);
                }
            }
        }

        float rowTot[4];
#pragma unroll
        for (int s = 0; s < 4; s++) {
            float a, b;
            unpack2(rowTot2[s], a, b);
            rowTot[s] = a + b;
            rowTot[s] += __shfl_xor_sync(0xffffffffu, rowTot[s], 1);
            rowTot[s] += __shfl_xor_sync(0xffffffffu, rowTot[s], 2);
        }
        if ((lane & 3) == 0) {
#pragma unroll
            for (int s = 0; s < 4; s++)
                redRowT[wc * 128 + li[s]] = rowTot[s];
        }
        if (!isDiag) {
            float colT[16];
#pragma unroll
            for (int n = 0; n < 8; n++) {
                float a, b;
                unpack2(colTot2[n], a, b);
                colT[2 * n] = a; colT[2 * n + 1] = b;
            }
#pragma unroll
            for (int x = 0; x < 16; x++) {
                colT[x] += __shfl_xor_sync(0xffffffffu, colT[x], 4);
                colT[x] += __shfl_xor_sync(0xffffffffu, colT[x], 8);
                colT[x] += __shfl_xor_sync(0xffffffffu, colT[x], 16);
            }
            if (lane < 4) {
#pragma unroll
                for (int n = 0; n < 8; n++) {
                    int lc = wc * 64 + n * 8 + lane * 2;
                    redColT[wr * 128 + lc]     = colT[2 * n];
                    redColT[wr * 128 + lc + 1] = colT[2 * n + 1];
                }
            }
        }
        __syncthreads();
        if (tid < 128) {
            float rt = redRowT[tid] + redRowT[128 + tid];
            g_totP[bj * Nn + bi * 128 + tid] = rt;
            if (!isDiag) {
                float ct = redColT[tid] + redColT[128 + tid] + redColT[256 + tid] + redColT[384 + tid];
                g_totP[bi * Nn + bj * 128 + tid] = ct;
            }
        }

        bi = nbi; bj = nbj; stage ^= 1;
    }
}

// ---------------- pos kernel: one CTA per class, gathered FP8 MMA ----------------
__global__ void __launch_bounds__(256, 1) pos_kernel() {
    extern __shared__ char smem[];
    uint32_t sb = smem_u32(smem);
    int tid = threadIdx.x, lane = tid & 31, wid = tid >> 5;
    int wr = wid & 3, wc = wid >> 2;
    int laneHi = lane >> 4;

    uint32_t rowOffA[2]; int axor[2];
#pragma unroll
    for (int i = 0; i < 2; i++) {
        int r = wr * 32 + i * 16 + (lane & 15);
        rowOffA[i] = r * 256; axor[i] = r & 7;
    }
    uint32_t rowOffB[4]; int bxor[4];
#pragma unroll
    for (int g = 0; g < 4; g++) {
        int r = wc * 64 + g * 16 + (lane & 15);
        rowOffB[g] = r * 256; bxor[g] = r & 7;
    }
    int li[4];
#pragma unroll
    for (int s = 0; s < 4; s++) li[s] = wr * 32 + (s >> 1) * 16 + (s & 1) * 8 + (lane >> 2);
    int lcBase = wc * 64 + (lane & 3) * 2;

    float* redR = (float*)(smem + PS_RED);   // 256 floats
    float* selfSm = (float*)(smem + PS_SELF); // 128 floats

    int c = blockIdx.x;
    int cnt = g_cnt[c];
    const int* perm = &g_perm[c * MAXC];
    int nsub = (cnt + 127) >> 7;

    for (int si = 0; si < nsub; si++) {
        // gather A rows (pad with zero rows)
#pragma unroll
        for (int it = 0; it < 8; it++) {
            int idx = it * 256 + tid;
            int r = idx >> 4, ch = idx & 15;
            int gr = si * 128 + r;
            const char* src = (gr < cnt) ? (const char*)&g_Q[perm[gr] * Dd] + ch * 16
                                         : (const char*)g_zero + ch * 16;
            CP16(sb + PS_A + r * 256 + ((ch ^ (r & 7)) << 4), src);
        }
        float rowAcc = 0.f;
        if (tid < 128) selfSm[tid] = 0.f;

        for (int sj = 0; sj < nsub; sj++) {
#pragma unroll
            for (int it = 0; it < 8; it++) {
                int idx = it * 256 + tid;
                int r = idx >> 4, ch = idx & 15;
                int gr = sj * 128 + r;
                const char* src = (gr < cnt) ? (const char*)&g_Q[perm[gr] * Dd] + ch * 16
                                             : (const char*)g_zero + ch * 16;
                CP16(sb + PS_B + r * 256 + ((ch ^ (r & 7)) << 4), src);
            }
            CP_COMMIT();
            CP_WAIT0();
            __syncthreads();

            float cAcc[2][8][4];
#pragma unroll
            for (int i = 0; i < 2; i++)
#pragma unroll
                for (int n = 0; n < 8; n++)
#pragma unroll
                    for (int v = 0; v < 4; v++) cAcc[i][n][v] = 0.f;

#pragma unroll
            for (int ks = 0; ks < 8; ks++) {
                uint32_t a[2][4], b[4][4];
                int ch = ks * 2 + laneHi;
#pragma unroll
                for (int i = 0; i < 2; i++) LDM4(a[i], sb + PS_A + rowOffA[i] + ((ch ^ axor[i]) << 4));
#pragma unroll
                for (int g = 0; g < 4; g++) LDM4(b[g], sb + PS_B + rowOffB[g] + ((ch ^ bxor[g]) << 4));
#pragma unroll
                for (int i = 0; i < 2; i++)
#pragma unroll
                    for (int n = 0; n < 8; n++)
                        QMMA(cAcc[i][n], a[i], b[n >> 1][n & 1], b[n >> 1][(n & 1) + 2]);
            }

            // epilogue with validity masks + self capture
            float rowTot[4] = {0.f, 0.f, 0.f, 0.f};
#pragma unroll
            for (int n = 0; n < 8; n++) {
                int lc0 = lcBase + n * 8, lc1 = lc0 + 1;
                bool v0 = (sj * 128 + lc0) < cnt;
                bool v1 = (sj * 128 + lc1) < cnt;
#pragma unroll
                for (int i = 0; i < 2; i++) {
                    float e0 = ex2f(cAcc[i][n][0]);
                    float e1 = ex2f(cAcc[i][n][1]);
                    float e2 = ex2f(cAcc[i][n][2]);
                    float e3 = ex2f(cAcc[i][n][3]);
                    if (v0) { rowTot[2 * i] += e0; rowTot[2 * i + 1] += e2; }
                    if (v1) { rowTot[2 * i] += e1; rowTot[2 * i + 1] += e3; }
                    if (si == sj) {
                        if (li[2 * i] == lc0)     selfSm[lc0] = e0;
                        if (li[2 * i] == lc1)     selfSm[lc1] = e1;
                        if (li[2 * i + 1] == lc0) selfSm[lc0] = e2;
                        if (li[2 * i + 1] == lc1) selfSm[lc1] = e3;
                    }
                }
            }
#pragma unroll
            for (int s = 0; s < 4; s++) {
                rowTot[s] += __shfl_xor_sync(0xffffffffu, rowTot[s], 1);
                rowTot[s] += __shfl_xor_sync(0xffffffffu, rowTot[s], 2);
            }
            if ((lane & 3) == 0) {
#pragma unroll
                for (int s = 0; s < 4; s++)
                    redR[wc * 128 + li[s]] = rowTot[s];
            }
            __syncthreads();
            if (tid < 128) rowAcc += redR[tid] + redR[128 + tid];
            __syncthreads();
        }

        if (tid < 128) {
            int gr = si * 128 + tid;
            if (gr < cnt) {
                int row = perm[gr];
                g_posI[row] = rowAcc;
                g_posE[row] = rowAcc - selfSm[tid];
            }
        }
        __syncthreads();
    }
}

// ---------------- finalize ----------------
__global__ void finalize1_kernel() {
    int r = blockIdx.x * 128 + threadIdx.x;
    float tt = 0.f;
#pragma unroll
    for (int s = 0; s < NBLK; s++) tt += g_totP[s * Nn + r];
    float neg = tt - g_posI[r];
    float local = logf(neg) - logf(g_posE[r]);
    int t = threadIdx.x;
#pragma unroll
    for (int o = 16; o > 0; o >>= 1) local += __shfl_down_sync(0xffffffffu, local, o);
    __shared__ float sm[4];
    if ((t & 31) == 0) sm[t >> 5] = local;
    __syncthreads();
    if (t == 0) g_lossP[blockIdx.x] = sm[0] + sm[1] + sm[2] + sm[3];
}

__global__ void finalize2_kernel(float* __restrict__ out) {
    int t = threadIdx.x;
    float v = g_lossP[t] + g_lossP[t + 32];
#pragma unroll
    for (int o = 16; o > 0; o >>= 1) v += __shfl_down_sync(0xffffffffu, v, o);
    if (t == 0) out[0] = v;
}

extern "C" void kernel_launch(void* const* d_in, const int* in_sizes, int n_in,
                              void* d_out, int out_size) {
    const float* emb = (const float*)d_in[0];
    const void* tgt = d_in[1];

    cudaFuncSetAttribute(main_kernel, cudaFuncAttributeMaxDynamicSharedMemorySize, SM_TOTAL);
    cudaFuncSetAttribute(pos_kernel, cudaFuncAttributeMaxDynamicSharedMemorySize, PS_TOTAL);

    detcls_kernel<<<1, 256>>>(tgt);
    norm_kernel<<<Nn / 8, 256>>>(emb);
    bucket_kernel<<<64, 256>>>();
    main_kernel<<<GRID_MAIN, 256, SM_TOTAL>>>();
    pos_kernel<<<64, 256, PS_TOTAL>>>();
    finalize1_kernel<<<64, 128>>>();
    finalize2_kernel<<<1, 32>>>((float*)d_out);
}

// round 9
// speedup vs baseline: 1.0209x; 1.0209x over previous
#include <cuda_runtime.h>
#include <cstdint>

// Problem constants
#define Nn 8192
#define Dd 256
#define NBLK 64           // 8192 / 128
#define NTILES 2080       // upper triangle incl diagonal: 64*65/2
#define GRID_MAIN 152
#define MAXC 256          // per-class row cap

// Main SMEM layout: 2 stages x (A 32KB + B 32KB) + reduction
#define STAGE_SZ 32768
#define SM_AOFF(s) ((s) * STAGE_SZ)
#define SM_BOFF(s) (65536 + (s) * STAGE_SZ)
#define SM_RED 131072
#define SM_TOTAL 135168

// Pos SMEM layout
#define PS_A 0
#define PS_B 32768
#define PS_RED 65536      // 256 floats
#define PS_SELF 66560     // 128 floats
#define PS_PERM 67072     // 256 ints
#define PS_SCAN 68096     // 256 ints
#define PS_TOTAL 69120

// scale folds 1/T and log2(e):  sqrt(10 * log2(e))
#define SCALE_C 3.79828197f

// Scratch (__device__ globals: allocation-free rule)
__device__ uint8_t g_Q[Nn * Dd];      // e4m3 rows of u * SCALE_C
__device__ uint8_t g_zero[256];       // zero row for padding (zero-initialized)
__device__ int   g_cls[Nn];
__device__ float g_totP[NBLK * Nn];
__device__ float g_posI[Nn];
__device__ float g_posE[Nn];
__device__ float g_lossP[64];
__device__ unsigned char g_ti[NTILES], g_tj[NTILES];

// ---------------- PTX helpers (family-safe) ----------------
__device__ __forceinline__ uint32_t smem_u32(const void* p) {
    uint32_t a;
    asm("{ .reg .u64 t; cvta.to.shared.u64 t, %1; cvt.u32.u64 %0, t; }" : "=r"(a) : "l"(p));
    return a;
}
#define CP16(dst, src) asm volatile("cp.async.cg.shared.global [%0], [%1], 16;" :: "r"(dst), "l"(src))
#define CP_COMMIT() asm volatile("cp.async.commit_group;" ::: "memory")
#define CP_WAIT0() asm volatile("cp.async.wait_group 0;" ::: "memory")
#define CP_WAIT1() asm volatile("cp.async.wait_group 1;" ::: "memory")

#define LDM4(r, a) \
    asm volatile("ldmatrix.sync.aligned.m8n8.x4.shared.b16 {%0,%1,%2,%3}, [%4];" \
        : "=r"((r)[0]), "=r"((r)[1]), "=r"((r)[2]), "=r"((r)[3]) : "r"(a))

#define QMMA(c, a, b0, b1) \
    asm volatile("mma.sync.aligned.m16n8k32.row.col.f32.e4m3.e4m3.f32 " \
        "{%0,%1,%2,%3}, {%4,%5,%6,%7}, {%8,%9}, {%0,%1,%2,%3};" \
        : "+f"((c)[0]), "+f"((c)[1]), "+f"((c)[2]), "+f"((c)[3]) \
        : "r"((a)[0]), "r"((a)[1]), "r"((a)[2]), "r"((a)[3]), "r"(b0), "r"(b1))

__device__ __forceinline__ float ex2f(float x) {
    float r;
    asm("ex2.approx.f32 %0, %1;" : "=f"(r) : "f"(x));
    return r;
}
__device__ __forceinline__ unsigned long long pack2(float lo, float hi) {
    unsigned long long r;
    asm("mov.b64 %0, {%1,%2};" : "=l"(r) : "f"(lo), "f"(hi));
    return r;
}
__device__ __forceinline__ void unpack2(unsigned long long v, float& lo, float& hi) {
    asm("mov.b64 {%0,%1}, %2;" : "=f"(lo), "=f"(hi) : "l"(v));
}
#define ADD2(d, a) asm("add.rn.f32x2 %0, %0, %1;" : "+l"(d) : "l"(a))

// e4m3 pack: first PTX src -> HIGH byte, second -> LOW byte
__device__ __forceinline__ uint16_t fp8x2(float loVal, float hiVal) {
    uint16_t r;
    asm("cvt.rn.satfinite.e4m3x2.f32 %0, %1, %2;" : "=h"(r) : "f"(hiVal), "f"(loVal));
    return r;
}

// ---------------- setup: dtype detect + class extraction + tile map ----------------
__global__ void detcls_kernel(const void* __restrict__ tgt) {
    __shared__ int sflag;
    const int* t32 = (const int*)tgt;
    int tid = threadIdx.x;
    int acc = 0;
    for (int k = tid; k < Nn / 2; k += 256) acc |= t32[2 * k + 1];
    acc = __reduce_or_sync(0xffffffffu, acc);
    __shared__ int sor[8];
    if ((tid & 31) == 0) sor[tid >> 5] = acc;
    __syncthreads();
    if (tid == 0) {
        int v = 0;
#pragma unroll
        for (int i = 0; i < 8; i++) v |= sor[i];
        sflag = (v == 0) ? 1 : 0;
    }
    __syncthreads();
    int is64 = sflag;
    const long long* t64 = (const long long*)tgt;
    for (int r = tid; r < Nn; r += 256)
        g_cls[r] = is64 ? (int)t64[r] : t32[r];
    for (int tt = tid; tt < NTILES; tt += 256) {
        int i = 0, rem = tt;
        while (rem >= NBLK - i) { rem -= NBLK - i; i++; }
        g_ti[tt] = (unsigned char)i;
        g_tj[tt] = (unsigned char)(i + rem);
    }
}

// ---------------- normalize + e4m3 quantize: warp per row ----------------
__global__ void norm_kernel(const float* __restrict__ emb) {
    int tid = threadIdx.x, lane = tid & 31, wid = tid >> 5;
    int row = blockIdx.x * 8 + wid;
    const float4* src = (const float4*)&emb[row * Dd + lane * 8];
    float4 v0 = src[0], v1 = src[1];
    float v[8] = {v0.x, v0.y, v0.z, v0.w, v1.x, v1.y, v1.z, v1.w};
    float sq = 0.f;
#pragma unroll
    for (int i = 0; i < 8; i++) sq += v[i] * v[i];
#pragma unroll
    for (int o = 16; o > 0; o >>= 1) sq += __shfl_xor_sync(0xffffffffu, sq, o);
    float scale = SCALE_C / fmaxf(sqrtf(sq), 1e-8f);
    uint16_t p01 = fp8x2(v[0] * scale, v[1] * scale);
    uint16_t p23 = fp8x2(v[2] * scale, v[3] * scale);
    uint16_t p45 = fp8x2(v[4] * scale, v[5] * scale);
    uint16_t p67 = fp8x2(v[6] * scale, v[7] * scale);
    uint32_t lo = (uint32_t)p01 | ((uint32_t)p23 << 16);
    uint32_t hi = (uint32_t)p45 | ((uint32_t)p67 << 16);
    *(uint2*)&g_Q[row * Dd + lane * 8] = make_uint2(lo, hi);
}

// ---------------- main fused symmetric FP8-MMA kernel (tot only, 512 thr) ----------------
__device__ __forceinline__ void loadChunk(uint32_t sb, int stage, int blkA, int blkB, int tid) {
    uint32_t aBase = sb + SM_AOFF(stage);
    uint32_t bBase = sb + SM_BOFF(stage);
#pragma unroll
    for (int it = 0; it < 4; it++) {
        int idx = it * 512 + tid;
        int r = idx >> 4, c = idx & 15;
        uint32_t off = r * 256 + ((c ^ (r & 7)) << 4);
        CP16(aBase + off, (const char*)&g_Q[(blkA * 128 + r) * Dd] + c * 16);
        CP16(bBase + off, (const char*)&g_Q[(blkB * 128 + r) * Dd] + c * 16);
    }
    CP_COMMIT();
}

__global__ void __launch_bounds__(512, 1) main_kernel() {
    extern __shared__ char smem[];
    uint32_t sb = smem_u32(smem);
    int tid = threadIdx.x, lane = tid & 31, wid = tid >> 5;
    int wr = wid & 3, wc = wid >> 2;          // 4 row-warps x 4 col-warps
    int laneHi = lane >> 4;

    uint32_t rowOffA[2]; int axor[2];
#pragma unroll
    for (int i = 0; i < 2; i++) {
        int r = wr * 32 + i * 16 + (lane & 15);
        rowOffA[i] = r * 256; axor[i] = r & 7;
    }
    uint32_t rowOffB[2]; int bxor[2];
#pragma unroll
    for (int g = 0; g < 2; g++) {
        int r = wc * 32 + g * 16 + (lane & 15);
        rowOffB[g] = r * 256; bxor[g] = r & 7;
    }
    int li[4];
#pragma unroll
    for (int s = 0; s < 4; s++) li[s] = wr * 32 + (s >> 1) * 16 + (s & 1) * 8 + (lane >> 2);

    float* redRowT = (float*)(smem + SM_RED);            // 512 floats
    float* redColT = redRowT + 512;                      // 512 floats

    int t0 = blockIdx.x;
    if (t0 >= NTILES) return;
    int bi = g_ti[t0], bj = g_tj[t0];
    loadChunk(sb, 0, bi, bj, tid);

    int stage = 0;
    for (int t = t0; t < NTILES; t += GRID_MAIN) {
        bool isDiag = (bi == bj);
        int nt = t + GRID_MAIN;
        int nbi = 0, nbj = 0;
        if (nt < NTILES) {
            nbi = g_ti[nt]; nbj = g_tj[nt];
            loadChunk(sb, stage ^ 1, nbi, nbj, tid);
            CP_WAIT1();
        } else {
            CP_WAIT0();
        }
        __syncthreads();

        float cAcc[2][4][4];
#pragma unroll
        for (int i = 0; i < 2; i++)
#pragma unroll
            for (int n = 0; n < 4; n++)
#pragma unroll
                for (int v = 0; v < 4; v++) cAcc[i][n][v] = 0.f;

        uint32_t aB = sb + SM_AOFF(stage), bB = sb + SM_BOFF(stage);
#pragma unroll
        for (int ks = 0; ks < 8; ks++) {
            uint32_t a[2][4], b[2][4];
            int ch = ks * 2 + laneHi;
#pragma unroll
            for (int i = 0; i < 2; i++) LDM4(a[i], aB + rowOffA[i] + ((ch ^ axor[i]) << 4));
#pragma unroll
            for (int g = 0; g < 2; g++) LDM4(b[g], bB + rowOffB[g] + ((ch ^ bxor[g]) << 4));
#pragma unroll
            for (int i = 0; i < 2; i++)
#pragma unroll
                for (int n = 0; n < 4; n++)
                    QMMA(cAcc[i][n], a[i], b[n >> 1][n & 1], b[n >> 1][(n & 1) + 2]);
        }

        // ---- minimal epilogue: ex2 + packed row/col totals, no masks ----
        unsigned long long rowTot2[4] = {0ull, 0ull, 0ull, 0ull};
        unsigned long long colTot2[4] = {0ull, 0ull, 0ull, 0ull};

        if (isDiag) {
#pragma unroll
            for (int n = 0; n < 4; n++) {
#pragma unroll
                for (int i = 0; i < 2; i++) {
                    float e0 = ex2f(cAcc[i][n][0]);
                    float e1 = ex2f(cAcc[i][n][1]);
                    float e2 = ex2f(cAcc[i][n][2]);
                    float e3 = ex2f(cAcc[i][n][3]);
                    ADD2(rowTot2[2 * i], pack2(e0, e1));
                    ADD2(rowTot2[2 * i + 1], pack2(e2, e3));
                }
            }
        } else {
#pragma unroll
            for (int n = 0; n < 4; n++) {
#pragma unroll
                for (int i = 0; i < 2; i++) {
                    float e0 = ex2f(cAcc[i][n][0]);
                    float e1 = ex2f(cAcc[i][n][1]);
                    float e2 = ex2f(cAcc[i][n][2]);
                    float e3 = ex2f(cAcc[i][n][3]);
                    unsigned long long p01 = pack2(e0, e1);
                    unsigned long long p23 = pack2(e2, e3);
                    ADD2(rowTot2[2 * i], p01);
                    ADD2(rowTot2[2 * i + 1], p23);
                    ADD2(colTot2[n], p01);
                    ADD2(colTot2[n], p23);
                }
            }
        }

        float rowTot[4];
#pragma unroll
        for (int s = 0; s < 4; s++) {
            float a, b;
            unpack2(rowTot2[s], a, b);
            rowTot[s] = a + b;
            rowTot[s] += __shfl_xor_sync(0xffffffffu, rowTot[s], 1);
            rowTot[s] += __shfl_xor_sync(0xffffffffu, rowTot[s], 2);
        }
        if ((lane & 3) == 0) {
#pragma unroll
            for (int s = 0; s < 4; s++)
                redRowT[wc * 128 + li[s]] = rowTot[s];
        }
        if (!isDiag) {
            float colT[8];
#pragma unroll
            for (int n = 0; n < 4; n++) {
                float a, b;
                unpack2(colTot2[n], a, b);
                colT[2 * n] = a; colT[2 * n + 1] = b;
            }
#pragma unroll
            for (int x = 0; x < 8; x++) {
                colT[x] += __shfl_xor_sync(0xffffffffu, colT[x], 4);
                colT[x] += __shfl_xor_sync(0xffffffffu, colT[x], 8);
                colT[x] += __shfl_xor_sync(0xffffffffu, colT[x], 16);
            }
            if (lane < 4) {
#pragma unroll
                for (int n = 0; n < 4; n++) {
                    int lc = wc * 32 + n * 8 + lane * 2;
                    redColT[wr * 128 + lc]     = colT[2 * n];
                    redColT[wr * 128 + lc + 1] = colT[2 * n + 1];
                }
            }
        }
        __syncthreads();
        if (tid < 128) {
            float rt = redRowT[tid] + redRowT[128 + tid] + redRowT[256 + tid] + redRowT[384 + tid];
            g_totP[bj * Nn + bi * 128 + tid] = rt;
            if (!isDiag) {
                float ct = redColT[tid] + redColT[128 + tid] + redColT[256 + tid] + redColT[384 + tid];
                g_totP[bi * Nn + bj * 128 + tid] = ct;
            }
        }

        bi = nbi; bj = nbj; stage ^= 1;
    }
}

// ---------------- pos kernel: one CTA per class, integrated bucketing ----------------
__global__ void __launch_bounds__(256, 1) pos_kernel() {
    extern __shared__ char smem[];
    uint32_t sb = smem_u32(smem);
    int tid = threadIdx.x, lane = tid & 31, wid = tid >> 5;
    int wr = wid & 3, wc = wid >> 2;
    int laneHi = lane >> 4;
    int c = blockIdx.x;

    int* permSm = (int*)(smem + PS_PERM);
    int* scanSm = (int*)(smem + PS_SCAN);
    float* redR = (float*)(smem + PS_RED);
    float* selfSm = (float*)(smem + PS_SELF);

    // ---- stable bucket of class c into permSm ----
    int base = tid * 32;
    int m = 0;
#pragma unroll 4
    for (int k = 0; k < 32; k++) m += (g_cls[base + k] == c) ? 1 : 0;
    scanSm[tid] = m;
    __syncthreads();
    for (int off = 1; off < 256; off <<= 1) {
        int v = (tid >= off) ? scanSm[tid - off] : 0;
        __syncthreads();
        scanSm[tid] += v;
        __syncthreads();
    }
    int w = scanSm[tid] - m;
    int cnt = scanSm[255];
    if (cnt > MAXC) cnt = MAXC;
    for (int k = 0; k < 32; k++) {
        if (g_cls[base + k] == c) {
            if (w < MAXC) permSm[w] = base + k;
            w++;
        }
    }
    __syncthreads();

    uint32_t rowOffA[2]; int axor[2];
#pragma unroll
    for (int i = 0; i < 2; i++) {
        int r = wr * 32 + i * 16 + (lane & 15);
        rowOffA[i] = r * 256; axor[i] = r & 7;
    }
    uint32_t rowOffB[4]; int bxor[4];
#pragma unroll
    for (int g = 0; g < 4; g++) {
        int r = wc * 64 + g * 16 + (lane & 15);
        rowOffB[g] = r * 256; bxor[g] = r & 7;
    }
    int li[4];
#pragma unroll
    for (int s = 0; s < 4; s++) li[s] = wr * 32 + (s >> 1) * 16 + (s & 1) * 8 + (lane >> 2);
    int lcBase = wc * 64 + (lane & 3) * 2;

    int nsub = (cnt + 127) >> 7;

    for (int si = 0; si < nsub; si++) {
#pragma unroll
        for (int it = 0; it < 8; it++) {
            int idx = it * 256 + tid;
            int r = idx >> 4, ch = idx & 15;
            int gr = si * 128 + r;
            const char* src = (gr < cnt) ? (const char*)&g_Q[permSm[gr] * Dd] + ch * 16
                                         : (const char*)g_zero + ch * 16;
            CP16(sb + PS_A + r * 256 + ((ch ^ (r & 7)) << 4), src);
        }
        float rowAcc = 0.f;
        if (tid < 128) selfSm[tid] = 0.f;

        for (int sj = 0; sj < nsub; sj++) {
#pragma unroll
            for (int it = 0; it < 8; it++) {
                int idx = it * 256 + tid;
                int r = idx >> 4, ch = idx & 15;
                int gr = sj * 128 + r;
                const char* src = (gr < cnt) ? (const char*)&g_Q[permSm[gr] * Dd] + ch * 16
                                             : (const char*)g_zero + ch * 16;
                CP16(sb + PS_B + r * 256 + ((ch ^ (r & 7)) << 4), src);
            }
            CP_COMMIT();
            CP_WAIT0();
            __syncthreads();

            float cAcc[2][8][4];
#pragma unroll
            for (int i = 0; i < 2; i++)
#pragma unroll
                for (int n = 0; n < 8; n++)
#pragma unroll
                    for (int v = 0; v < 4; v++) cAcc[i][n][v] = 0.f;

#pragma unroll
            for (int ks = 0; ks < 8; ks++) {
                uint32_t a[2][4], b[4][4];
                int ch = ks * 2 + laneHi;
#pragma unroll
                for (int i = 0; i < 2; i++) LDM4(a[i], sb + PS_A + rowOffA[i] + ((ch ^ axor[i]) << 4));
#pragma unroll
                for (int g = 0; g < 4; g++) LDM4(b[g], sb + PS_B + rowOffB[g] + ((ch ^ bxor[g]) << 4));
#pragma unroll
                for (int i = 0; i < 2; i++)
#pragma unroll
                    for (int n = 0; n < 8; n++)
                        QMMA(cAcc[i][n], a[i], b[n >> 1][n & 1], b[n >> 1][(n & 1) + 2]);
            }

            float rowTot[4] = {0.f, 0.f, 0.f, 0.f};
#pragma unroll
            for (int n = 0; n < 8; n++) {
                int lc0 = lcBase + n * 8, lc1 = lc0 + 1;
                bool v0 = (sj * 128 + lc0) < cnt;
                bool v1 = (sj * 128 + lc1) < cnt;
#pragma unroll
                for (int i = 0; i < 2; i++) {
                    float e0 = ex2f(cAcc[i][n][0]);
                    float e1 = ex2f(cAcc[i][n][1]);
                    float e2 = ex2f(cAcc[i][n][2]);
                    float e3 = ex2f(cAcc[i][n][3]);
                    if (v0) { rowTot[2 * i] += e0; rowTot[2 * i + 1] += e2; }
                    if (v1) { rowTot[2 * i] += e1; rowTot[2 * i + 1] += e3; }
                    if (si == sj) {
                        if (li[2 * i] == lc0)     selfSm[lc0] = e0;
                        if (li[2 * i] == lc1)     selfSm[lc1] = e1;
                        if (li[2 * i + 1] == lc0) selfSm[lc0] = e2;
                        if (li[2 * i + 1] == lc1) selfSm[lc1] = e3;
                    }
                }
            }
#pragma unroll
            for (int s = 0; s < 4; s++) {
                rowTot[s] += __shfl_xor_sync(0xffffffffu, rowTot[s], 1);
                rowTot[s] += __shfl_xor_sync(0xffffffffu, rowTot[s], 2);
            }
            if ((lane & 3) == 0) {
#pragma unroll
                for (int s = 0; s < 4; s++)
                    redR[wc * 128 + li[s]] = rowTot[s];
            }
            __syncthreads();
            if (tid < 128) rowAcc += redR[tid] + redR[128 + tid];
            __syncthreads();
        }

        if (tid < 128) {
            int gr = si * 128 + tid;
            if (gr < cnt) {
                int row = permSm[gr];
                g_posI[row] = rowAcc;
                g_posE[row] = rowAcc - selfSm[tid];
            }
        }
        __syncthreads();
    }
}

// ---------------- finalize ----------------
__global__ void finalize1_kernel() {
    int r = blockIdx.x * 128 + threadIdx.x;
    float tt = 0.f;
#pragma unroll
    for (int s = 0; s < NBLK; s++) tt += g_totP[s * Nn + r];
    float neg = tt - g_posI[r];
    float local = logf(neg) - logf(g_posE[r]);
    int t = threadIdx.x;
#pragma unroll
    for (int o = 16; o > 0; o >>= 1) local += __shfl_down_sync(0xffffffffu, local, o);
    __shared__ float sm[4];
    if ((t & 31) == 0) sm[t >> 5] = local;
    __syncthreads();
    if (t == 0) g_lossP[blockIdx.x] = sm[0] + sm[1] + sm[2] + sm[3];
}

__global__ void finalize2_kernel(float* __restrict__ out) {
    int t = threadIdx.x;
    float v = g_lossP[t] + g_lossP[t + 32];
#pragma unroll
    for (int o = 16; o > 0; o >>= 1) v += __shfl_down_sync(0xffffffffu, v, o);
    if (t == 0) out[0] = v;
}

extern "C" void kernel_launch(void* const* d_in, const int* in_sizes, int n_in,
                              void* d_out, int out_size) {
    const float* emb = (const float*)d_in[0];
    const void* tgt = d_in[1];

    cudaFuncSetAttribute(main_kernel, cudaFuncAttributeMaxDynamicSharedMemorySize, SM_TOTAL);
    cudaFuncSetAttribute(pos_kernel, cudaFuncAttributeMaxDynamicSharedMemorySize, PS_TOTAL);

    detcls_kernel<<<1, 256>>>(tgt);
    norm_kernel<<<Nn / 8, 256>>>(emb);
    main_kernel<<<GRID_MAIN, 512, SM_TOTAL>>>();
    pos_kernel<<<64, 256, PS_TOTAL>>>();
    finalize1_kernel<<<64, 128>>>();
    finalize2_kernel<<<1, 32>>>((float*)d_out);
}